// round 2
// baseline (speedup 1.0000x reference)
#include <cuda_runtime.h>

// Problem constants
#define N_PTS   32768
#define DIM     128
#define KCODES  4096
#define DECAY   0.8f
#define ONE_M_DECAY 0.2f
#define EPS_    1e-5f
#define COMMIT_W 0.25f

// Output layout (flattened f32 concat of the reference tuple)
#define OFF_Q    0                        // quantize [N, D]
#define OFF_IND  (N_PTS * DIM)            // embed_ind [N] (as float)
#define OFF_LOSS (OFF_IND + N_PTS)        // commit_loss [1]
#define OFF_CS   (OFF_LOSS + 1)           // cs_new [K]
#define OFF_EN   (OFF_CS + KCODES)        // embed_normalized [K, D]

// Scratch (device globals; no allocation allowed)
__device__ int   g_best[N_PTS];
__device__ float g_embed_sum[KCODES * DIM];
__device__ float g_bins[KCODES];
__device__ float g_cs_new[KCODES];
__device__ float g_loss;
__device__ float g_ntotal;

// ---------------------------------------------------------------------------
// Kernel 0: zero the scratch accumulators (determinism across graph replays)
// ---------------------------------------------------------------------------
__global__ void zero_kernel() {
    int idx = blockIdx.x * blockDim.x + threadIdx.x;
    int total = KCODES * DIM;
    for (int i = idx; i < total; i += gridDim.x * blockDim.x)
        g_embed_sum[i] = 0.0f;
    if (idx < KCODES) g_bins[idx] = 0.0f;
    if (idx == 0) { g_loss = 0.0f; g_ntotal = 0.0f; }
}

// ---------------------------------------------------------------------------
// Kernel 1: fused fp32 distance GEMM + argmax.
// 64 rows per CTA, 64-code tiles, 256 threads, 4x4 register micro-tile.
// score = 2 * (x . e) - |e|^2  (same argmax as reference's dist)
// ---------------------------------------------------------------------------
#define ROWS_CTA 64
#define CODES_TILE 64
#define THREADS_MAIN 256

// dynamic smem partition (floats):
//   xs [128][64]       (x tile, transposed: xs[d*64 + r])            8192
//   es [128][68]       (e tile, transposed+pad: es[d*68 + c])        8704
//   se2 [64]           (|e|^2 per tile code)                           64
//   rv  [64*16]        (argmax reduce values)                        1024
//   ri  [64*16]        (argmax reduce indices, int)                  1024
#define SMEM_FLOATS (8192 + 8704 + 64 + 1024 + 1024)
#define SMEM_BYTES  (SMEM_FLOATS * 4)

__global__ __launch_bounds__(THREADS_MAIN)
void vq_argmax_kernel(const float* __restrict__ x,
                      const float* __restrict__ embed,
                      float* __restrict__ out) {
    extern __shared__ float sm[];
    float* xs  = sm;                      // 8192
    float* es  = sm + 8192;               // 8704
    float* se2 = sm + 8192 + 8704;        // 64
    float* rv  = se2 + 64;                // 1024
    int*   ri  = (int*)(rv + 1024);       // 1024

    const int tid = threadIdx.x;
    const int rowBase = blockIdx.x * ROWS_CTA;
    const int rg = tid & 15;              // row group 0..15
    const int cg = tid >> 4;              // code group 0..15
    const int r0 = rg * 4;
    const int c0 = cg * 4;

    // Load x tile transposed: 64 rows x 128 d  (2048 float4 chunks)
    const float4* x4 = (const float4*)x;
    #pragma unroll
    for (int t = tid; t < ROWS_CTA * 32; t += THREADS_MAIN) {
        int r  = t >> 5;          // 0..63
        int d4 = t & 31;          // 0..31
        float4 v = x4[(rowBase + r) * 32 + d4];
        int d = d4 * 4;
        xs[(d + 0) * 64 + r] = v.x;
        xs[(d + 1) * 64 + r] = v.y;
        xs[(d + 2) * 64 + r] = v.z;
        xs[(d + 3) * 64 + r] = v.w;
    }

    float bv[4]; int bi[4];
    #pragma unroll
    for (int i = 0; i < 4; i++) { bv[i] = -3.0e38f; bi[i] = 0; }

    const float4* e4 = (const float4*)embed;

    for (int kt = 0; kt < KCODES / CODES_TILE; kt++) {
        __syncthreads();  // previous tile's es/se2 fully consumed

        // Load e tile transposed: 64 codes x 128 d
        #pragma unroll
        for (int t = tid; t < CODES_TILE * 32; t += THREADS_MAIN) {
            int c  = t >> 5;
            int d4 = t & 31;
            float4 v = e4[(kt * CODES_TILE + c) * 32 + d4];
            int d = d4 * 4;
            es[(d + 0) * 68 + c] = v.x;
            es[(d + 1) * 68 + c] = v.y;
            es[(d + 2) * 68 + c] = v.z;
            es[(d + 3) * 68 + c] = v.w;
        }
        if (tid < CODES_TILE) se2[tid] = 0.0f;
        __syncthreads();

        // |e|^2 for this tile: 4 partial chunks of 32 d's per code
        {
            int c = tid & 63;
            int part = tid >> 6;       // 0..3
            float s = 0.0f;
            #pragma unroll 8
            for (int d = part * 32; d < part * 32 + 32; d++) {
                float v = es[d * 68 + c];
                s += v * v;
            }
            atomicAdd(&se2[c], s);
        }

        // Dot-product micro-kernel: 4x4 accumulators over d=0..127
        float acc[4][4];
        #pragma unroll
        for (int i = 0; i < 4; i++)
            #pragma unroll
            for (int j = 0; j < 4; j++) acc[i][j] = 0.0f;

        #pragma unroll 8
        for (int d = 0; d < DIM; d++) {
            float4 a = *(const float4*)&xs[d * 64 + r0];
            float4 b = *(const float4*)&es[d * 68 + c0];
            acc[0][0] += a.x * b.x; acc[0][1] += a.x * b.y; acc[0][2] += a.x * b.z; acc[0][3] += a.x * b.w;
            acc[1][0] += a.y * b.x; acc[1][1] += a.y * b.y; acc[1][2] += a.y * b.z; acc[1][3] += a.y * b.w;
            acc[2][0] += a.z * b.x; acc[2][1] += a.z * b.y; acc[2][2] += a.z * b.z; acc[2][3] += a.z * b.w;
            acc[3][0] += a.w * b.x; acc[3][1] += a.w * b.y; acc[3][2] += a.w * b.z; acc[3][3] += a.w * b.w;
        }
        __syncthreads();   // se2 atomics complete

        // Score + running argmax. Codes ascend (tiles ascend, j ascends),
        // strict > keeps the lowest index on exact ties (matches jnp.argmax).
        int kbase = kt * CODES_TILE;
        #pragma unroll
        for (int j = 0; j < 4; j++) {
            float e2v = se2[c0 + j];
            int   idx = kbase + c0 + j;
            #pragma unroll
            for (int i = 0; i < 4; i++) {
                float s = 2.0f * acc[i][j] - e2v;
                if (s > bv[i]) { bv[i] = s; bi[i] = idx; }
            }
        }
    }

    // Cross-thread argmax reduce: 16 candidate (v,idx) per row
    __syncthreads();
    #pragma unroll
    for (int i = 0; i < 4; i++) {
        int row = r0 + i;
        rv[row * 16 + cg] = bv[i];
        ri[row * 16 + cg] = bi[i];
    }
    __syncthreads();
    if (tid < ROWS_CTA) {
        float best = rv[tid * 16];
        int bidx   = ri[tid * 16];
        #pragma unroll
        for (int t = 1; t < 16; t++) {
            float v = rv[tid * 16 + t];
            int  id = ri[tid * 16 + t];
            if (v > best || (v == best && id < bidx)) { best = v; bidx = id; }
        }
        int n = rowBase + tid;
        g_best[n] = bidx;
        out[OFF_IND + n] = (float)bidx;
    }
}

// ---------------------------------------------------------------------------
// Kernel 2: quantize gather + commit-loss partial + EMA scatter (bins, sums)
// one row per 128-thread block
// ---------------------------------------------------------------------------
__global__ __launch_bounds__(128)
void gather_scatter_kernel(const float* __restrict__ x,
                           const float* __restrict__ embed,
                           float* __restrict__ out) {
    int n = blockIdx.x;
    int d = threadIdx.x;
    int best = g_best[n];

    float xv = x[n * DIM + d];
    float ev = embed[best * DIM + d];
    out[OFF_Q + n * DIM + d] = ev;

    float diff = ev - xv;
    float sq = diff * diff;
    // warp + block reduce of sq
    #pragma unroll
    for (int o = 16; o > 0; o >>= 1) sq += __shfl_down_sync(0xffffffffu, sq, o);
    __shared__ float ws[4];
    int lane = d & 31, w = d >> 5;
    if (lane == 0) ws[w] = sq;
    __syncthreads();
    if (d == 0) atomicAdd(&g_loss, ws[0] + ws[1] + ws[2] + ws[3]);

    atomicAdd(&g_embed_sum[best * DIM + d], xv);
    if (d == 0) atomicAdd(&g_bins[best], 1.0f);
}

// ---------------------------------------------------------------------------
// Kernel 3a: cs_new + n_total
// ---------------------------------------------------------------------------
__global__ __launch_bounds__(256)
void cs_kernel(const float* __restrict__ cluster_size, float* __restrict__ out) {
    int k = blockIdx.x * 256 + threadIdx.x;
    float cs = cluster_size[k] * DECAY + ONE_M_DECAY * g_bins[k];
    g_cs_new[k] = cs;
    out[OFF_CS + k] = cs;
    // block reduce for n_total
    float s = cs;
    #pragma unroll
    for (int o = 16; o > 0; o >>= 1) s += __shfl_down_sync(0xffffffffu, s, o);
    __shared__ float ws[8];
    int lane = threadIdx.x & 31, w = threadIdx.x >> 5;
    if (lane == 0) ws[w] = s;
    __syncthreads();
    if (threadIdx.x == 0) {
        float t = 0.0f;
        #pragma unroll
        for (int i = 0; i < 8; i++) t += ws[i];
        atomicAdd(&g_ntotal, t);
    }
}

// ---------------------------------------------------------------------------
// Kernel 3b: embed_normalized + commit_loss finalize
// ---------------------------------------------------------------------------
__global__ __launch_bounds__(128)
void finalize_kernel(const float* __restrict__ embed_avg, float* __restrict__ out) {
    int k = blockIdx.x;
    int d = threadIdx.x;
    float nt = g_ntotal;
    float cs = g_cs_new[k];
    float cluster = (cs + EPS_) / (nt + (float)KCODES * EPS_) * nt;
    float ea = embed_avg[k * DIM + d] * DECAY + ONE_M_DECAY * g_embed_sum[k * DIM + d];
    out[OFF_EN + k * DIM + d] = ea / cluster;
    if (k == 0 && d == 0)
        out[OFF_LOSS] = COMMIT_W * g_loss * (1.0f / (float)(N_PTS * DIM));
}

// ---------------------------------------------------------------------------
extern "C" void kernel_launch(void* const* d_in, const int* in_sizes, int n_in,
                              void* d_out, int out_size) {
    const float* x            = (const float*)d_in[0];  // [N, D]
    const float* embed        = (const float*)d_in[1];  // [1, K, D]
    const float* cluster_size = (const float*)d_in[2];  // [1, K]
    const float* embed_avg    = (const float*)d_in[3];  // [1, K, D]
    float* out = (float*)d_out;

    cudaFuncSetAttribute(vq_argmax_kernel,
                         cudaFuncAttributeMaxDynamicSharedMemorySize, SMEM_BYTES);

    zero_kernel<<<2064, 256>>>();
    vq_argmax_kernel<<<N_PTS / ROWS_CTA, THREADS_MAIN, SMEM_BYTES>>>(x, embed, out);
    gather_scatter_kernel<<<N_PTS, 128>>>(x, embed, out);
    cs_kernel<<<KCODES / 256, 256>>>(cluster_size, out);
    finalize_kernel<<<KCODES, 128>>>(embed_avg, out);
}